// round 14
// baseline (speedup 1.0000x reference)
#include <cuda_runtime.h>

#define BB     4
#define CC     32
#define HH     512
#define WW     512
#define NBOX   64
#define H_OUT_ 16
#define HW     (HH * WW)
#define MAX_W_ 192
#define CHALF  16
#define CSTRIDE (H_OUT_ * MAX_W_)

// ---------------------------------------------------------------------------
// Kernel A: pure-write zero-fill of the masked output region [width, 192).
// Homogeneous write-only DRAM stream (no gathers mixed in) -> runs at
// near-pure-write bandwidth instead of the mixed-stream 4.2 TB/s.
// One block per (c, bn); float4 stores except a <=3-float unaligned head.
__global__ __launch_bounds__(128) void zerofill_kernel(
    const float* __restrict__ boxes,
    float* __restrict__ out)
{
    const int c  = blockIdx.x;            // 0..31
    const int bn = blockIdx.y;            // 0..255
    const int tid = threadIdx.x;

    const float* bx = boxes + bn * 5;
    const float bw = bx[2] - bx[0];
    const float bh = bx[3] - bx[1];
    const int width = (int)(__fdiv_rn(bw, bh) * (float)H_OUT_);   // 16..184

    const int wal    = (width + 3) & ~3;        // first float4-aligned col
    const int head   = wal - width;             // 0..3 scalar floats per row
    const int nchunk = (MAX_W_ - wal) >> 2;     // float4 chunks per row
    const int per_row = head + nchunk;
    const int total   = H_OUT_ * per_row;

    const int rbase = (bn * CC + c) * CSTRIDE;
    const float4 z = make_float4(0.f, 0.f, 0.f, 0.f);

    for (int u = tid; u < total; u += 128) {
        const int i = u / per_row;
        const int k = u - i * per_row;
        const int base = rbase + i * MAX_W_;
        if (k < head) out[base + width + k] = 0.0f;
        else *(float4*)&out[base + wal + ((k - head) << 2)] = z;
    }
}

// ---------------------------------------------------------------------------
// Kernel B: the proven R3 gather structure, but masked threads write only the
// mask and exit (zero region handled by kernel A) -> 155MB -> 107MB traffic
// for the mixed-stream kernel.
__global__ __launch_bounds__(MAX_W_) void roirotate_kernel(
    const float* __restrict__ img,      // (B, C, H, W)
    const float* __restrict__ boxes,    // (B, N, 5)
    float* __restrict__ out,            // (B, N, C, H_OUT, MAX_W)
    float* __restrict__ maskf,          // (B, N, MAX_W) as float, or null
    unsigned char* __restrict__ masku8) // (B, N, MAX_W) as u8, or null
{
    const int bi   = blockIdx.x;          // 0 .. B*N*H_OUT*2-1
    const int half = bi & 1;              // channel half
    const int i    = (bi >> 1) & (H_OUT_ - 1);
    const int bn   = bi >> 5;             // b*NBOX + n
    const int b    = bn >> 6;
    const int j    = threadIdx.x;

    const float* bx = boxes + bn * 5;
    const float left = bx[0];
    const float top  = bx[1];
    const float bw   = bx[2] - left;
    const float bh   = bx[3] - top;

    // width = int32(bw/bh * H_OUT): IEEE-correct division so truncation
    // matches the JAX reference bit-exactly (mask is binary!)
    const int   width  = (int)(__fdiv_rn(bw, bh) * (float)H_OUT_);
    const float each_w = __fdiv_rn(bw, (float)(width - 1));
    const float each_h = __fdiv_rn(bh, (float)(H_OUT_ - 1));

    const bool valid = (j < width);

    if (i == 0 && half == 0) {
        if (maskf)  maskf [bn * MAX_W_ + j] = valid ? 1.0f : 0.0f;
        if (masku8) masku8[bn * MAX_W_ + j] = valid ? (unsigned char)1 : (unsigned char)0;
    }

    if (!valid) return;   // zero region written by zerofill_kernel

    // out index (32-bit: max 25,165,824 < 2^31)
    const int obase = (bn * CC + half * CHALF) * CSTRIDE + i * MAX_W_ + j;

    const float x = (float)j * each_w + left;
    const float y = (float)i * each_h + top;
    int x0 = (int)floorf(x);
    int y0 = (int)floorf(y);
    int x1 = x0 + 1;
    int y1 = y0 + 1;
    x0 = max(0, min(x0, WW - 1));
    x1 = max(0, min(x1, WW - 1));
    y0 = max(0, min(y0, HH - 1));
    y1 = max(0, min(y1, HH - 1));

    const float wxl = (float)x1 - x;
    const float wxr = x - (float)x0;
    const float wyt = (float)y1 - y;
    const float wyb = y - (float)y0;

    const float wa = wxl * wyt;
    const float wb = wxl * wyb;
    const float wc = wxr * wyt;
    const float wd = wxr * wyb;

    const int o00 = y0 * WW + x0;
    const int dx  = x1 - x0;          // 0 or 1
    const int dy  = (y1 - y0) * WW;   // 0 or WW

    const float* p = img + b * (CC * HW) + (half * CHALF) * HW + o00;

    #pragma unroll
    for (int cc = 0; cc < CHALF; cc++) {
        const float ia = __ldg(p);
        const float ic = __ldg(p + dx);
        const float ib = __ldg(p + dy);
        const float id = __ldg(p + dy + dx);
        out[obase + cc * CSTRIDE] = ia * wa + ib * wb + ic * wc + id * wd;
        p += HW;
    }
}

extern "C" void kernel_launch(void* const* d_in, const int* in_sizes, int n_in,
                              void* d_out, int out_size)
{
    const float* img   = (const float*)d_in[0];
    const float* boxes = (const float*)d_in[1];

    const long long R = (long long)BB * NBOX * CC * H_OUT_ * MAX_W_; // 25,165,824
    const long long M = (long long)BB * NBOX * MAX_W_;               // 49,152

    const dim3 zgrid(CC, BB * NBOX);          // (32, 256) = 8192 blocks
    const dim3 zblock(128);
    const dim3 grid(BB * NBOX * H_OUT_ * 2);  // 8192 blocks
    const dim3 block(MAX_W_);                 // 192 threads

    float* of = (float*)d_out;

    if ((long long)out_size == R * 4 + M) {
        unsigned char* ob = (unsigned char*)d_out;
        zerofill_kernel<<<zgrid, zblock>>>(boxes, (float*)ob);
        roirotate_kernel<<<grid, block>>>(img, boxes, (float*)ob, nullptr, ob + R * 4);
    } else if ((long long)out_size >= R + M) {
        zerofill_kernel<<<zgrid, zblock>>>(boxes, of);
        roirotate_kernel<<<grid, block>>>(img, boxes, of, of + R, nullptr);
    } else {
        zerofill_kernel<<<zgrid, zblock>>>(boxes, of);
        roirotate_kernel<<<grid, block>>>(img, boxes, of, nullptr, nullptr);
    }
}

// round 16
// speedup vs baseline: 1.1816x; 1.1816x over previous
#include <cuda_runtime.h>

#define BB     4
#define CC     32
#define HH     512
#define WW     512
#define NBOX   64
#define H_OUT_ 16
#define HW     (HH * WW)
#define MAX_W_ 192
#define CHALF  16
#define CSTRIDE (H_OUT_ * MAX_W_)

// R15: single launch, block-specialized. Grid = 12288 blocks of 192 threads:
//   bid % 3 != 2 -> gather block (R14 kernel B: R3 structure, masked threads
//                   exit without stores)   [8192 blocks]
//   bid % 3 == 2 -> zerofill block: one (bn, i), zero cols [width,192) for
//                   all 32 channels with float4 stores   [4096 blocks]
// Interleaving the two kinds in issue order runs the pure-write stream
// concurrently with the latency-bound gather stream (R14 showed them serial:
// 32.8us + ~12us; concurrent they share the idle DRAM slots).
__global__ __launch_bounds__(MAX_W_) void roirotate_kernel(
    const float* __restrict__ img,      // (B, C, H, W)
    const float* __restrict__ boxes,    // (B, N, 5)
    float* __restrict__ out,            // (B, N, C, H_OUT, MAX_W)
    float* __restrict__ maskf,          // (B, N, MAX_W) as float, or null
    unsigned char* __restrict__ masku8) // (B, N, MAX_W) as u8, or null
{
    const int bid  = blockIdx.x;
    const int kind = bid % 3;
    const int idx  = bid / 3;           // 0..4095
    const int tid  = threadIdx.x;

    if (kind == 2) {
        // ---------------- zerofill block: (bn, i) ---------------------------
        const int bn = idx >> 4;          // 0..255
        const int i  = idx & 15;

        const float* bx = boxes + bn * 5;
        const float bw = bx[2] - bx[0];
        const float bh = bx[3] - bx[1];
        const int width = (int)(__fdiv_rn(bw, bh) * (float)H_OUT_);  // 16..184

        const int wal     = (width + 3) & ~3;     // first float4-aligned col
        const int head    = wal - width;          // 0..3 scalar cols
        const int nchunk  = (MAX_W_ - wal) >> 2;  // float4 chunks
        const int per_row = head + nchunk;        // work units per channel
        const int total   = CC * per_row;

        const int rbase = bn * CC * CSTRIDE + i * MAX_W_;
        const float4 z = make_float4(0.f, 0.f, 0.f, 0.f);

        for (int u = tid; u < total; u += MAX_W_) {
            const int c = u / per_row;
            const int k = u - c * per_row;
            const int base = rbase + c * CSTRIDE;
            if (k < head) out[base + width + k] = 0.0f;
            else *(float4*)&out[base + wal + ((k - head) << 2)] = z;
        }
        return;
    }

    // ---------------- gather block: (bn, i, channel-half) -------------------
    const int gb   = idx * 2 + kind;      // 0..8191
    const int half = gb & 1;
    const int i    = (gb >> 1) & (H_OUT_ - 1);
    const int bn   = gb >> 5;
    const int b    = bn >> 6;
    const int j    = tid;

    const float* bx = boxes + bn * 5;
    const float left = bx[0];
    const float top  = bx[1];
    const float bw   = bx[2] - left;
    const float bh   = bx[3] - top;

    // width = int32(bw/bh * H_OUT): IEEE-correct division so truncation
    // matches the JAX reference bit-exactly (mask is binary!)
    const int   width  = (int)(__fdiv_rn(bw, bh) * (float)H_OUT_);
    const float each_w = __fdiv_rn(bw, (float)(width - 1));
    const float each_h = __fdiv_rn(bh, (float)(H_OUT_ - 1));

    const bool valid = (j < width);

    if (i == 0 && half == 0) {
        if (maskf)  maskf [bn * MAX_W_ + j] = valid ? 1.0f : 0.0f;
        if (masku8) masku8[bn * MAX_W_ + j] = valid ? (unsigned char)1 : (unsigned char)0;
    }

    if (!valid) return;   // zero region handled by zerofill blocks

    const int obase = (bn * CC + half * CHALF) * CSTRIDE + i * MAX_W_ + j;

    const float x = (float)j * each_w + left;
    const float y = (float)i * each_h + top;
    int x0 = (int)floorf(x);
    int y0 = (int)floorf(y);
    int x1 = x0 + 1;
    int y1 = y0 + 1;
    x0 = max(0, min(x0, WW - 1));
    x1 = max(0, min(x1, WW - 1));
    y0 = max(0, min(y0, HH - 1));
    y1 = max(0, min(y1, HH - 1));

    const float wxl = (float)x1 - x;
    const float wxr = x - (float)x0;
    const float wyt = (float)y1 - y;
    const float wyb = y - (float)y0;

    const float wa = wxl * wyt;
    const float wb = wxl * wyb;
    const float wc = wxr * wyt;
    const float wd = wxr * wyb;

    const int o00 = y0 * WW + x0;
    const int dx  = x1 - x0;          // 0 or 1
    const int dy  = (y1 - y0) * WW;   // 0 or WW

    const float* p = img + b * (CC * HW) + (half * CHALF) * HW + o00;

    #pragma unroll
    for (int cc = 0; cc < CHALF; cc++) {
        const float ia = __ldg(p);
        const float ic = __ldg(p + dx);
        const float ib = __ldg(p + dy);
        const float id = __ldg(p + dy + dx);
        out[obase + cc * CSTRIDE] = ia * wa + ib * wb + ic * wc + id * wd;
        p += HW;
    }
}

extern "C" void kernel_launch(void* const* d_in, const int* in_sizes, int n_in,
                              void* d_out, int out_size)
{
    const float* img   = (const float*)d_in[0];
    const float* boxes = (const float*)d_in[1];

    const long long R = (long long)BB * NBOX * CC * H_OUT_ * MAX_W_; // 25,165,824
    const long long M = (long long)BB * NBOX * MAX_W_;               // 49,152

    const dim3 grid(12288);     // 8192 gather + 4096 zerofill, interleaved
    const dim3 block(MAX_W_);   // 192 threads

    if ((long long)out_size == R * 4 + M) {
        unsigned char* ob = (unsigned char*)d_out;
        roirotate_kernel<<<grid, block>>>(img, boxes, (float*)ob, nullptr, ob + R * 4);
    } else if ((long long)out_size >= R + M) {
        float* of = (float*)d_out;
        roirotate_kernel<<<grid, block>>>(img, boxes, of, of + R, nullptr);
    } else {
        float* of = (float*)d_out;
        roirotate_kernel<<<grid, block>>>(img, boxes, of, nullptr, nullptr);
    }
}